// round 12
// baseline (speedup 1.0000x reference)
#include <cuda_runtime.h>
#include <cuda_fp16.h>
#include <cstdint>
#include <float.h>

#define FEAT 128
#define MAXN 50000
#define MAXE 600000
#define CAP 96

// ---------------- scratch -------------------------------------------------
__device__ __half g_Ch[MAXN * FEAT];      // theta(x) fp16 (gather reads)
__device__ __half g_Dh[MAXN * FEAT];      // phi - theta + (tb+pb), fp16
__device__ __half g_Xf[MAXN * FEAT];      // current X, fp16
__device__ __half g_Wf[4 * 256 * 128];    // [l][row<128:theta else phi][k]
__device__ int g_cur[MAXN];   // bucket fill count == degree (zero-init at load;
                              // re-zeroed by gather layer 3 for the next run)
__device__ int g_csr[MAXN * CAP];         // premultiplied src*32, bucketed by dst

// ------- fused setup: convert X and W to fp16 + bucket scatter --------------
__global__ void setup_kernel(const float* __restrict__ x,
                             const float* __restrict__ tw,
                             const float* __restrict__ pw,
                             const int* __restrict__ src,
                             const int* __restrict__ dst,
                             int n, int e) {
    int i = blockIdx.x * blockDim.x + threadIdx.x;
    if (i < e) {
        int d = dst[i];
        int p = atomicAdd(&g_cur[d], 1);
        g_csr[d * CAP + p] = src[i] * 32;   // premultiplied uint2-row index
    }
    if (i < 4 * 256 * 128) {
        int l = i >> 15;
        int r = (i >> 7) & 255;
        int k = i & 127;
        const float* W = (r < 128) ? tw : pw;
        g_Wf[i] = __float2half_rn(W[(size_t)l * FEAT * FEAT + (size_t)(r & 127) * FEAT + k]);
    }
    if (i < n * FEAT) {
        g_Xf[i] = __float2half_rn(x[i]);
    }
}

// ---------------- mma.sync fp16 GEMM, full prefetch, single barrier ---------
// K = 128, 4 chunks of K32, all issued upfront and waited once.
#define NKC 4
#define STAGE_BYTES 30720
#define STAGE_B_OFF 10240
#define BIAS_OFF (4 * STAGE_BYTES)
#define GEMM_SMEM (4 * STAGE_BYTES + 512)

__device__ __forceinline__ uint32_t smem_u32(const void* p) {
    uint32_t a;
    asm("{ .reg .u64 t; cvta.to.shared.u64 t, %1; cvt.u32.u64 %0, t; }" : "=r"(a) : "l"(p));
    return a;
}
__device__ __forceinline__ uint64_t gmem_u64(const void* p) {
    uint64_t a;
    asm("cvta.to.global.u64 %0, %1;" : "=l"(a) : "l"(p));
    return a;
}
#define CP_ASYNC16(dst, src, sz)                                             \
    asm volatile("cp.async.cg.shared.global [%0], [%1], 16, %2;"             \
                 :: "r"(dst), "l"(src), "r"(sz) : "memory")
#define CP_COMMIT() asm volatile("cp.async.commit_group;" ::: "memory")
#define CP_WAIT0() asm volatile("cp.async.wait_group 0;" ::: "memory")

#define LDMX4(r0, r1, r2, r3, addr)                                          \
    asm volatile("ldmatrix.sync.aligned.m8n8.x4.shared.b16 {%0,%1,%2,%3}, [%4];" \
                 : "=r"(r0), "=r"(r1), "=r"(r2), "=r"(r3) : "r"(addr))
#define MMA16816F(d, a0, a1, a2, a3, b0, b1)                                 \
    asm volatile("mma.sync.aligned.m16n8k16.row.col.f32.f16.f16.f32 "        \
                 "{%0,%1,%2,%3},{%4,%5,%6,%7},{%8,%9},{%0,%1,%2,%3};"        \
                 : "+f"((d)[0]), "+f"((d)[1]), "+f"((d)[2]), "+f"((d)[3])    \
                 : "r"(a0), "r"(a1), "r"(a2), "r"(a3), "r"(b0), "r"(b1))

__global__ void __launch_bounds__(512, 1)
gemm_mma_kernel(int layer, const float* __restrict__ tb,
                const float* __restrict__ pb, int n) {
    extern __shared__ __half sm[];
    uint32_t smb = smem_u32(sm);
    float* sbias = (float*)((char*)sm + BIAS_OFF);
    int t = threadIdx.x, lane = t & 31, wid = t >> 5;
    int m0 = blockIdx.x * 128;

    uint64_t Wg = gmem_u64(g_Wf + (size_t)layer * 32768);
    uint64_t Xg = gmem_u64(g_Xf);

    int warp_m = wid & 3;
    int warp_n = wid >> 2;

    int arow = t >> 2, aq = t & 3;
    int gr = m0 + arow;
    uint32_t a_ok = (gr < n) ? 16u : 0u;
    uint32_t a_dst_off = (uint32_t)(arow * 80 + aq * 16);
    uint64_t a_src_off = ((uint64_t)(uint32_t)gr * FEAT + aq * 8) * 2;
    int i0 = t, i1 = t + 512;
    uint32_t b_dst0 = (uint32_t)(STAGE_B_OFF + (i0 >> 2) * 80 + (i0 & 3) * 16);
    uint32_t b_dst1 = (uint32_t)(STAGE_B_OFF + (i1 >> 2) * 80 + (i1 & 3) * 16);
    uint64_t b_src0 = ((uint64_t)(i0 >> 2) * 128 + (i0 & 3) * 8) * 2;
    uint64_t b_src1 = ((uint64_t)(i1 >> 2) * 128 + (i1 & 3) * 8) * 2;

    // issue ALL 4 chunks upfront
    #pragma unroll
    for (int kc = 0; kc < NKC; kc++) {
        uint32_t st = smb + (uint32_t)kc * STAGE_BYTES;
        uint64_t kb = (uint64_t)(kc * 32) * 2;
        CP_ASYNC16(st + a_dst_off, Xg + a_src_off + kb, a_ok);
        CP_ASYNC16(st + b_dst0, Wg + b_src0 + kb, 16u);
        CP_ASYNC16(st + b_dst1, Wg + b_src1 + kb, 16u);
    }
    CP_COMMIT();

    // bias precompute overlaps the async loads
    if (t < 128) sbias[t] = __ldg(&tb[t]) + __ldg(&pb[t]);

    float accT[2][4][4], accP[2][4][4];
    #pragma unroll
    for (int mt = 0; mt < 2; mt++)
        #pragma unroll
        for (int nt = 0; nt < 4; nt++)
            #pragma unroll
            for (int r = 0; r < 4; r++) { accT[mt][nt][r] = 0.f; accP[mt][nt][r] = 0.f; }

    int lr  = (lane & 7) + ((lane >> 3) & 1) * 8;
    int lk8 = (lane >> 4) * 8;
    int bg  = lane >> 3;
    int br_ = (lane & 7) + ((bg >> 1) & 1) * 8;
    int bk8 = (bg & 1) * 8;

    CP_WAIT0();
    __syncthreads();     // the ONLY barrier: all stages + bias now visible

    #pragma unroll
    for (int kc = 0; kc < NKC; kc++) {
        uint32_t stA = smb + (uint32_t)kc * STAGE_BYTES;
        uint32_t stB = stA + STAGE_B_OFF;

        #pragma unroll
        for (int ks = 0; ks < 2; ks++) {
            int k = ks * 16;
            uint32_t aF[2][4];
            #pragma unroll
            for (int mt = 0; mt < 2; mt++) {
                uint32_t ad = stA + (uint32_t)((warp_m * 32 + mt * 16 + lr) * 80 + (k + lk8) * 2);
                LDMX4(aF[mt][0], aF[mt][1], aF[mt][2], aF[mt][3], ad);
            }
            {
                uint32_t bt[4][2];
                #pragma unroll
                for (int nh = 0; nh < 2; nh++) {
                    uint32_t bd = stB + (uint32_t)((warp_n * 32 + nh * 16 + br_) * 80 + (k + bk8) * 2);
                    LDMX4(bt[nh * 2][0], bt[nh * 2][1], bt[nh * 2 + 1][0], bt[nh * 2 + 1][1], bd);
                }
                #pragma unroll
                for (int mt = 0; mt < 2; mt++)
                    #pragma unroll
                    for (int nt = 0; nt < 4; nt++)
                        MMA16816F(accT[mt][nt], aF[mt][0], aF[mt][1], aF[mt][2], aF[mt][3],
                                  bt[nt][0], bt[nt][1]);
            }
            {
                uint32_t bp[4][2];
                #pragma unroll
                for (int nh = 0; nh < 2; nh++) {
                    uint32_t bd = stB + (uint32_t)((128 + warp_n * 32 + nh * 16 + br_) * 80 + (k + bk8) * 2);
                    LDMX4(bp[nh * 2][0], bp[nh * 2][1], bp[nh * 2 + 1][0], bp[nh * 2 + 1][1], bd);
                }
                #pragma unroll
                for (int mt = 0; mt < 2; mt++)
                    #pragma unroll
                    for (int nt = 0; nt < 4; nt++)
                        MMA16816F(accP[mt][nt], aF[mt][0], aF[mt][1], aF[mt][2], aF[mt][3],
                                  bp[nt][0], bp[nt][1]);
            }
        }
    }

    // epilogue: g_Ch = fp16(theta); g_Dh = fp16(phi - theta + (tb+pb))
    #pragma unroll
    for (int mt = 0; mt < 2; mt++) {
        #pragma unroll
        for (int nt = 0; nt < 4; nt++) {
            int f = warp_n * 32 + nt * 8 + (lane & 3) * 2;
            float bias0 = sbias[f];
            float bias1 = sbias[f + 1];
            int m = m0 + warp_m * 32 + mt * 16 + (lane >> 2);
            float* c = accT[mt][nt];
            float* p = accP[mt][nt];
            if (m < n) {
                *(__half2*)(g_Ch + (size_t)m * FEAT + f) = __floats2half2_rn(c[0], c[1]);
                *(__half2*)(g_Dh + (size_t)m * FEAT + f) =
                    __floats2half2_rn(p[0] - c[0] + bias0, p[1] - c[1] + bias1);
            }
            if (m + 8 < n) {
                *(__half2*)(g_Ch + (size_t)(m + 8) * FEAT + f) = __floats2half2_rn(c[2], c[3]);
                *(__half2*)(g_Dh + (size_t)(m + 8) * FEAT + f) =
                    __floats2half2_rn(p[2] - c[2] + bias0, p[3] - c[3] + bias1);
            }
        }
    }
}

// -------- gather-max: coalesced index preload + shfl broadcast, MLP=2 -------
__device__ __forceinline__ uint32_t hmax2u(uint32_t x, uint32_t y) {
    __half2 r = __hmax2(*(__half2*)&x, *(__half2*)&y);
    return *(uint32_t*)&r;
}

__global__ void gather_kernel(float* __restrict__ dout, int layer, int n) {
    int gw = (blockIdx.x * blockDim.x + threadIdx.x) >> 5;
    int lane = threadIdx.x & 31;
    if (gw >= n) return;

    int deg = g_cur[gw];
    const int* lst = g_csr + gw * CAP;
    const uint2* C2 = (const uint2*)g_Ch;

    // hoisted D load (independent of edge loop)
    uint2 dv = __ldg(&((const uint2*)g_Dh)[(size_t)gw * 32 + lane]);

    const uint32_t NEG = 0xFBFFFBFFu;  // -65504 x2
    uint32_t a0 = NEG, a1 = NEG, b0 = NEG, b1 = NEG;

    for (int base = 0; base < deg; base += 32) {
        int cnt = deg - base; if (cnt > 32) cnt = 32;
        // ONE coalesced load fetches up to 32 bucket indices for the warp
        int idx = base + lane;
        int my = __ldg(&lst[(idx < deg) ? idx : base]);
        int e = 0;
        for (; e + 1 < cnt; e += 2) {
            int s0 = __shfl_sync(0xffffffffu, my, e);
            int s1 = __shfl_sync(0xffffffffu, my, e + 1);
            uint2 v0 = __ldg(&C2[(size_t)(uint32_t)(s0 + lane)]);
            uint2 v1 = __ldg(&C2[(size_t)(uint32_t)(s1 + lane)]);
            a0 = hmax2u(a0, v0.x); a1 = hmax2u(a1, v0.y);
            b0 = hmax2u(b0, v1.x); b1 = hmax2u(b1, v1.y);
        }
        if (e < cnt) {
            int s0 = __shfl_sync(0xffffffffu, my, e);
            uint2 v0 = __ldg(&C2[(size_t)(uint32_t)(s0 + lane)]);
            a0 = hmax2u(a0, v0.x); a1 = hmax2u(a1, v0.y);
        }
    }
    a0 = hmax2u(a0, b0);
    a1 = hmax2u(a1, b1);

    float2 m01 = __half22float2(*(__half2*)&a0);
    float2 m23 = __half22float2(*(__half2*)&a1);
    float2 d01 = __half22float2(*(__half2*)&dv.x);
    float2 d23 = __half22float2(*(__half2*)&dv.y);

    float4 o;
    o.x = fmaxf(0.f, d01.x + m01.x);
    o.y = fmaxf(0.f, d01.y + m01.y);
    o.z = fmaxf(0.f, d23.x + m23.x);
    o.w = fmaxf(0.f, d23.y + m23.y);

    if (layer == 3) {
        ((float4*)dout)[(size_t)gw * 32 + lane] = o;
        if (lane == 0) g_cur[gw] = 0;     // re-arm bucket counters for next run
    } else {
        __half2 p0 = __floats2half2_rn(o.x, o.y);
        __half2 p1 = __floats2half2_rn(o.z, o.w);
        uint2 xv;
        xv.x = *(uint32_t*)&p0;
        xv.y = *(uint32_t*)&p1;
        *(uint2*)(g_Xf + (size_t)gw * FEAT + lane * 4) = xv;
    }
}

// ---------------- launch ----------------------------------------------------
extern "C" void kernel_launch(void* const* d_in, const int* in_sizes, int n_in,
                              void* d_out, int out_size) {
    const float* feats = (const float*)d_in[0];
    const int*   src   = (const int*)d_in[1];
    const int*   dst   = (const int*)d_in[2];
    const float* tw    = (const float*)d_in[3];
    const float* tb    = (const float*)d_in[4];
    const float* pw    = (const float*)d_in[5];
    const float* pb    = (const float*)d_in[6];

    int n = in_sizes[0] / FEAT;
    int e = in_sizes[1];
    if (n > MAXN) n = MAXN;
    if (e > MAXE) e = MAXE;

    static int smem_set = 0;
    if (!smem_set) {
        cudaFuncSetAttribute(gemm_mma_kernel,
                             cudaFuncAttributeMaxDynamicSharedMemorySize, GEMM_SMEM);
        smem_set = 1;
    }

    // fused setup: X/W fp16 convert + bucket scatter (g_cur pre-zeroed)
    setup_kernel<<<(n * FEAT + 255) / 256, 256>>>(feats, tw, pw, src, dst, n, e);

    int gemm_gx = (n + 127) / 128;
    int warp_blocks = (n * 32 + 255) / 256;

    for (int l = 0; l < 4; l++) {
        gemm_mma_kernel<<<gemm_gx, 512, GEMM_SMEM>>>(l, tb + l * FEAT, pb + l * FEAT, n);
        gather_kernel<<<warp_blocks, 256>>>((float*)d_out, l, n);
    }
}

// round 13
// speedup vs baseline: 1.0509x; 1.0509x over previous
#include <cuda_runtime.h>
#include <cuda_fp16.h>
#include <cstdint>
#include <float.h>

#define FEAT 128
#define MAXN 50000
#define MAXE 600000
#define CAP 96

// ---------------- scratch -------------------------------------------------
__device__ __half g_Ch[MAXN * FEAT];      // theta(x) fp16 (gather reads)
__device__ __half g_Dh[MAXN * FEAT];      // phi - theta + (tb+pb), fp16
__device__ __half g_Xf[MAXN * FEAT];      // current X, fp16
__device__ __half g_Wf[4 * 256 * 128];    // [l][row<128:theta else phi][k]
__device__ int g_cur[MAXN];   // bucket fill count == degree (zero-init at load;
                              // re-zeroed by gather layer 3 for the next run)
__device__ int g_csr[MAXN * CAP];         // premultiplied src*32, bucketed by dst

// ------- fused setup: convert X and W to fp16 + bucket scatter --------------
__global__ void setup_kernel(const float* __restrict__ x,
                             const float* __restrict__ tw,
                             const float* __restrict__ pw,
                             const int* __restrict__ src,
                             const int* __restrict__ dst,
                             int n, int e) {
    int i = blockIdx.x * blockDim.x + threadIdx.x;
    if (i < e) {
        int d = dst[i];
        int p = atomicAdd(&g_cur[d], 1);
        g_csr[d * CAP + p] = src[i] * 32;   // premultiplied uint2-row index
    }
    if (i < 4 * 256 * 128) {
        int l = i >> 15;
        int r = (i >> 7) & 255;
        int k = i & 127;
        const float* W = (r < 128) ? tw : pw;
        g_Wf[i] = __float2half_rn(W[(size_t)l * FEAT * FEAT + (size_t)(r & 127) * FEAT + k]);
    }
    if (i < n * FEAT) {
        g_Xf[i] = __float2half_rn(x[i]);
    }
}

// ------- mma.sync fp16 GEMM: BM=64, 256 threads, 2 CTAs/SM -------------------
// K = 128, 4 chunks of K32, all issued upfront; per-chunk waits (R11 pattern).
#define NKC 4
#define STAGE_BYTES 25600
#define STAGE_B_OFF 5120
#define GEMM_SMEM (4 * STAGE_BYTES)

__device__ __forceinline__ uint32_t smem_u32(const void* p) {
    uint32_t a;
    asm("{ .reg .u64 t; cvta.to.shared.u64 t, %1; cvt.u32.u64 %0, t; }" : "=r"(a) : "l"(p));
    return a;
}
__device__ __forceinline__ uint64_t gmem_u64(const void* p) {
    uint64_t a;
    asm("cvta.to.global.u64 %0, %1;" : "=l"(a) : "l"(p));
    return a;
}
#define CP_ASYNC16(dst, src, sz)                                             \
    asm volatile("cp.async.cg.shared.global [%0], [%1], 16, %2;"             \
                 :: "r"(dst), "l"(src), "r"(sz) : "memory")
#define CP_COMMIT() asm volatile("cp.async.commit_group;" ::: "memory")
#define CP_WAITN(nn) asm volatile("cp.async.wait_group %0;" :: "n"(nn) : "memory")

#define LDMX4(r0, r1, r2, r3, addr)                                          \
    asm volatile("ldmatrix.sync.aligned.m8n8.x4.shared.b16 {%0,%1,%2,%3}, [%4];" \
                 : "=r"(r0), "=r"(r1), "=r"(r2), "=r"(r3) : "r"(addr))
#define MMA16816F(d, a0, a1, a2, a3, b0, b1)                                 \
    asm volatile("mma.sync.aligned.m16n8k16.row.col.f32.f16.f16.f32 "        \
                 "{%0,%1,%2,%3},{%4,%5,%6,%7},{%8,%9},{%0,%1,%2,%3};"        \
                 : "+f"((d)[0]), "+f"((d)[1]), "+f"((d)[2]), "+f"((d)[3])    \
                 : "r"(a0), "r"(a1), "r"(a2), "r"(a3), "r"(b0), "r"(b1))

__global__ void __launch_bounds__(256, 2)
gemm_mma_kernel(int layer, const float* __restrict__ tb,
                const float* __restrict__ pb, int n) {
    extern __shared__ __half sm[];
    uint32_t smb = smem_u32(sm);
    int t = threadIdx.x, lane = t & 31, wid = t >> 5;
    int m0 = blockIdx.x * 64;

    uint64_t Wg = gmem_u64(g_Wf + (size_t)layer * 32768);
    uint64_t Xg = gmem_u64(g_Xf);

    int warp_m = wid & 1;     // 2 m-warps x 32 rows
    int warp_n = wid >> 1;    // 4 n-warps x 32 cols

    // A loader: 64 rows x 32 halves per chunk = 256 x 16B
    int arow = t >> 2, aq = t & 3;
    int gr = m0 + arow;
    uint32_t a_ok = (gr < n) ? 16u : 0u;
    uint32_t a_dst_off = (uint32_t)(arow * 80 + aq * 16);
    uint64_t a_src_off = ((uint64_t)(uint32_t)gr * FEAT + aq * 8) * 2;
    // B loader: 256 rows x 32 halves per chunk = 1024 x 16B -> 4 per thread
    uint32_t b_dst[4];
    uint64_t b_src[4];
    #pragma unroll
    for (int j = 0; j < 4; j++) {
        int i = t + j * 256;
        b_dst[j] = (uint32_t)(STAGE_B_OFF + (i >> 2) * 80 + (i & 3) * 16);
        b_src[j] = ((uint64_t)(i >> 2) * 128 + (i & 3) * 8) * 2;
    }

    // issue ALL 4 chunks upfront, one commit group per chunk
    #pragma unroll
    for (int kc = 0; kc < NKC; kc++) {
        uint32_t st = smb + (uint32_t)kc * STAGE_BYTES;
        uint64_t kb = (uint64_t)(kc * 32) * 2;
        CP_ASYNC16(st + a_dst_off, Xg + a_src_off + kb, a_ok);
        #pragma unroll
        for (int j = 0; j < 4; j++)
            CP_ASYNC16(st + b_dst[j], Wg + b_src[j] + kb, 16u);
        CP_COMMIT();
    }

    float accT[2][4][4], accP[2][4][4];
    #pragma unroll
    for (int mt = 0; mt < 2; mt++)
        #pragma unroll
        for (int nt = 0; nt < 4; nt++)
            #pragma unroll
            for (int r = 0; r < 4; r++) { accT[mt][nt][r] = 0.f; accP[mt][nt][r] = 0.f; }

    int lr  = (lane & 7) + ((lane >> 3) & 1) * 8;
    int lk8 = (lane >> 4) * 8;
    int bg  = lane >> 3;
    int br_ = (lane & 7) + ((bg >> 1) & 1) * 8;
    int bk8 = (bg & 1) * 8;

    #pragma unroll
    for (int kc = 0; kc < NKC; kc++) {
        if (kc == 0)      { CP_WAITN(3); }
        else if (kc == 1) { CP_WAITN(2); }
        else if (kc == 2) { CP_WAITN(1); }
        else              { CP_WAITN(0); }
        __syncthreads();

        uint32_t stA = smb + (uint32_t)kc * STAGE_BYTES;
        uint32_t stB = stA + STAGE_B_OFF;

        #pragma unroll
        for (int ks = 0; ks < 2; ks++) {
            int k = ks * 16;
            uint32_t aF[2][4];
            #pragma unroll
            for (int mt = 0; mt < 2; mt++) {
                uint32_t ad = stA + (uint32_t)((warp_m * 32 + mt * 16 + lr) * 80 + (k + lk8) * 2);
                LDMX4(aF[mt][0], aF[mt][1], aF[mt][2], aF[mt][3], ad);
            }
            {
                uint32_t bt[4][2];
                #pragma unroll
                for (int nh = 0; nh < 2; nh++) {
                    uint32_t bd = stB + (uint32_t)((warp_n * 32 + nh * 16 + br_) * 80 + (k + bk8) * 2);
                    LDMX4(bt[nh * 2][0], bt[nh * 2][1], bt[nh * 2 + 1][0], bt[nh * 2 + 1][1], bd);
                }
                #pragma unroll
                for (int mt = 0; mt < 2; mt++)
                    #pragma unroll
                    for (int nt = 0; nt < 4; nt++)
                        MMA16816F(accT[mt][nt], aF[mt][0], aF[mt][1], aF[mt][2], aF[mt][3],
                                  bt[nt][0], bt[nt][1]);
            }
            {
                uint32_t bp[4][2];
                #pragma unroll
                for (int nh = 0; nh < 2; nh++) {
                    uint32_t bd = stB + (uint32_t)((128 + warp_n * 32 + nh * 16 + br_) * 80 + (k + bk8) * 2);
                    LDMX4(bp[nh * 2][0], bp[nh * 2][1], bp[nh * 2 + 1][0], bp[nh * 2 + 1][1], bd);
                }
                #pragma unroll
                for (int mt = 0; mt < 2; mt++)
                    #pragma unroll
                    for (int nt = 0; nt < 4; nt++)
                        MMA16816F(accP[mt][nt], aF[mt][0], aF[mt][1], aF[mt][2], aF[mt][3],
                                  bp[nt][0], bp[nt][1]);
            }
        }
    }

    // epilogue: g_Ch = fp16(theta); g_Dh = fp16(phi - theta + (tb+pb))
    #pragma unroll
    for (int mt = 0; mt < 2; mt++) {
        #pragma unroll
        for (int nt = 0; nt < 4; nt++) {
            int f = warp_n * 32 + nt * 8 + (lane & 3) * 2;
            float bias0 = __ldg(&tb[f]) + __ldg(&pb[f]);
            float bias1 = __ldg(&tb[f + 1]) + __ldg(&pb[f + 1]);
            int m = m0 + warp_m * 32 + mt * 16 + (lane >> 2);
            float* c = accT[mt][nt];
            float* p = accP[mt][nt];
            if (m < n) {
                *(__half2*)(g_Ch + (size_t)m * FEAT + f) = __floats2half2_rn(c[0], c[1]);
                *(__half2*)(g_Dh + (size_t)m * FEAT + f) =
                    __floats2half2_rn(p[0] - c[0] + bias0, p[1] - c[1] + bias1);
            }
            if (m + 8 < n) {
                *(__half2*)(g_Ch + (size_t)(m + 8) * FEAT + f) = __floats2half2_rn(c[2], c[3]);
                *(__half2*)(g_Dh + (size_t)(m + 8) * FEAT + f) =
                    __floats2half2_rn(p[2] - c[2] + bias0, p[3] - c[3] + bias1);
            }
        }
    }
}

// ---------------- gather-max: 1 warp/node, uint2, MLP=2 (R11 exact) --------
__device__ __forceinline__ uint32_t hmax2u(uint32_t x, uint32_t y) {
    __half2 r = __hmax2(*(__half2*)&x, *(__half2*)&y);
    return *(uint32_t*)&r;
}

__global__ void gather_kernel(float* __restrict__ dout, int layer, int n) {
    int gw = (blockIdx.x * blockDim.x + threadIdx.x) >> 5;
    int lane = threadIdx.x & 31;
    if (gw >= n) return;

    int deg = g_cur[gw];
    const int* lst = g_csr + gw * CAP;
    const uint2* C2 = (const uint2*)g_Ch;

    // hoisted D load (independent of edge loop)
    uint2 dv = __ldg(&((const uint2*)g_Dh)[(size_t)gw * 32 + lane]);

    const uint32_t NEG = 0xFBFFFBFFu;  // -65504 x2
    uint32_t a0 = NEG, a1 = NEG, b0 = NEG, b1 = NEG;

    int e = 0;
    for (; e + 1 < deg; e += 2) {
        int s0 = __ldg(&lst[e]);          // premultiplied src*32
        int s1 = __ldg(&lst[e + 1]);
        uint2 v0 = __ldg(&C2[(size_t)(uint32_t)(s0 + lane)]);
        uint2 v1 = __ldg(&C2[(size_t)(uint32_t)(s1 + lane)]);
        a0 = hmax2u(a0, v0.x); a1 = hmax2u(a1, v0.y);
        b0 = hmax2u(b0, v1.x); b1 = hmax2u(b1, v1.y);
    }
    if (e < deg) {
        int s0 = __ldg(&lst[e]);
        uint2 v0 = __ldg(&C2[(size_t)(uint32_t)(s0 + lane)]);
        a0 = hmax2u(a0, v0.x); a1 = hmax2u(a1, v0.y);
    }
    a0 = hmax2u(a0, b0);
    a1 = hmax2u(a1, b1);

    float2 m01 = __half22float2(*(__half2*)&a0);
    float2 m23 = __half22float2(*(__half2*)&a1);
    float2 d01 = __half22float2(*(__half2*)&dv.x);
    float2 d23 = __half22float2(*(__half2*)&dv.y);

    float4 o;
    o.x = fmaxf(0.f, d01.x + m01.x);
    o.y = fmaxf(0.f, d01.y + m01.y);
    o.z = fmaxf(0.f, d23.x + m23.x);
    o.w = fmaxf(0.f, d23.y + m23.y);

    if (layer == 3) {
        ((float4*)dout)[(size_t)gw * 32 + lane] = o;
        if (lane == 0) g_cur[gw] = 0;     // re-arm bucket counters for next run
    } else {
        __half2 p0 = __floats2half2_rn(o.x, o.y);
        __half2 p1 = __floats2half2_rn(o.z, o.w);
        uint2 xv;
        xv.x = *(uint32_t*)&p0;
        xv.y = *(uint32_t*)&p1;
        *(uint2*)(g_Xf + (size_t)gw * FEAT + lane * 4) = xv;
    }
}

// ---------------- launch ----------------------------------------------------
extern "C" void kernel_launch(void* const* d_in, const int* in_sizes, int n_in,
                              void* d_out, int out_size) {
    const float* feats = (const float*)d_in[0];
    const int*   src   = (const int*)d_in[1];
    const int*   dst   = (const int*)d_in[2];
    const float* tw    = (const float*)d_in[3];
    const float* tb    = (const float*)d_in[4];
    const float* pw    = (const float*)d_in[5];
    const float* pb    = (const float*)d_in[6];

    int n = in_sizes[0] / FEAT;
    int e = in_sizes[1];
    if (n > MAXN) n = MAXN;
    if (e > MAXE) e = MAXE;

    static int smem_set = 0;
    if (!smem_set) {
        cudaFuncSetAttribute(gemm_mma_kernel,
                             cudaFuncAttributeMaxDynamicSharedMemorySize, GEMM_SMEM);
        smem_set = 1;
    }

    // fused setup: X/W fp16 convert + bucket scatter (g_cur pre-zeroed)
    setup_kernel<<<(n * FEAT + 255) / 256, 256>>>(feats, tw, pw, src, dst, n, e);

    int gemm_gx = (n + 63) / 64;
    int warp_blocks = (n * 32 + 255) / 256;

    for (int l = 0; l < 4; l++) {
        gemm_mma_kernel<<<gemm_gx, 256, GEMM_SMEM>>>(l, tb + l * FEAT, pb + l * FEAT, n);
        gather_kernel<<<warp_blocks, 256>>>((float*)d_out, l, n);
    }
}

// round 14
// speedup vs baseline: 1.1293x; 1.0746x over previous
#include <cuda_runtime.h>
#include <cuda_fp16.h>
#include <cstdint>
#include <float.h>

#define FEAT 128
#define MAXN 50000
#define MAXE 600000
#define CAP 96

// ---------------- scratch -------------------------------------------------
__device__ __half g_Ch[MAXN * FEAT];      // theta(x) fp16 (gather reads)
__device__ __half g_Dh[MAXN * FEAT];      // phi - theta + (tb+pb), fp16
__device__ __half g_Xf[MAXN * FEAT];      // current X, fp16
__device__ __half g_Wf[4 * 256 * 128];    // [l][row<128:theta else phi][k]
__device__ int g_cur[MAXN];   // bucket fill count == degree (zero-init at load;
                              // re-zeroed by gather layer 3 for the next run)
__device__ int g_csr[MAXN * CAP];         // premultiplied src*32, bucketed by dst

// ------- fused setup: convert X and W to fp16 + bucket scatter --------------
__global__ void setup_kernel(const float* __restrict__ x,
                             const float* __restrict__ tw,
                             const float* __restrict__ pw,
                             const int* __restrict__ src,
                             const int* __restrict__ dst,
                             int n, int e) {
    int i = blockIdx.x * blockDim.x + threadIdx.x;
    if (i < e) {
        int d = dst[i];
        int p = atomicAdd(&g_cur[d], 1);
        g_csr[d * CAP + p] = src[i] * 32;   // premultiplied uint2-row index
    }
    if (i < 4 * 256 * 128) {
        int l = i >> 15;
        int r = (i >> 7) & 255;
        int k = i & 127;
        const float* W = (r < 128) ? tw : pw;
        g_Wf[i] = __float2half_rn(W[(size_t)l * FEAT * FEAT + (size_t)(r & 127) * FEAT + k]);
    }
    if (i < n * FEAT) {
        g_Xf[i] = __float2half_rn(x[i]);
    }
}

// ------- persistent mma.sync fp16 GEMM: W resident in smem ------------------
// BM=64, 256 threads, 2 CTAs/SM. Grid = 296 persistent CTAs, each loops tiles.
// Smem: W[256 rows x 272B] @0, A double buffer [2][64 x 272B] @69632.
#define WROW 272
#define SM_W_BYTES (256 * WROW)
#define SM_A_OFF SM_W_BYTES
#define SM_A_BYTES (64 * WROW)
#define GEMM_SMEM (SM_W_BYTES + 2 * SM_A_BYTES)

__device__ __forceinline__ uint32_t smem_u32(const void* p) {
    uint32_t a;
    asm("{ .reg .u64 t; cvta.to.shared.u64 t, %1; cvt.u32.u64 %0, t; }" : "=r"(a) : "l"(p));
    return a;
}
__device__ __forceinline__ uint64_t gmem_u64(const void* p) {
    uint64_t a;
    asm("cvta.to.global.u64 %0, %1;" : "=l"(a) : "l"(p));
    return a;
}
#define CP_ASYNC16(dst, src, sz)                                             \
    asm volatile("cp.async.cg.shared.global [%0], [%1], 16, %2;"             \
                 :: "r"(dst), "l"(src), "r"(sz) : "memory")
#define CP_COMMIT() asm volatile("cp.async.commit_group;" ::: "memory")
#define CP_WAIT0() asm volatile("cp.async.wait_group 0;" ::: "memory")

#define LDMX4(r0, r1, r2, r3, addr)                                          \
    asm volatile("ldmatrix.sync.aligned.m8n8.x4.shared.b16 {%0,%1,%2,%3}, [%4];" \
                 : "=r"(r0), "=r"(r1), "=r"(r2), "=r"(r3) : "r"(addr))
#define MMA16816F(d, a0, a1, a2, a3, b0, b1)                                 \
    asm volatile("mma.sync.aligned.m16n8k16.row.col.f32.f16.f16.f32 "        \
                 "{%0,%1,%2,%3},{%4,%5,%6,%7},{%8,%9},{%0,%1,%2,%3};"        \
                 : "+f"((d)[0]), "+f"((d)[1]), "+f"((d)[2]), "+f"((d)[3])    \
                 : "r"(a0), "r"(a1), "r"(a2), "r"(a3), "r"(b0), "r"(b1))

__global__ void __launch_bounds__(256, 2)
gemm_mma_kernel(int layer, const float* __restrict__ tb,
                const float* __restrict__ pb, int n, int ntiles) {
    extern __shared__ __half sm[];
    uint32_t smb = smem_u32(sm);
    int t = threadIdx.x, lane = t & 31, wid = t >> 5;

    uint64_t Wg = gmem_u64(g_Wf + (size_t)layer * 32768);
    uint64_t Xg = gmem_u64(g_Xf);

    int warp_m = wid & 1;     // 2 m-warps x 32 rows
    int warp_n = wid >> 1;    // 4 n-warps x 32 cols

    // ---- prologue: load W once (4096 x 16B chunks, 16 per thread) ----
    #pragma unroll
    for (int j = 0; j < 16; j++) {
        int i = t + j * 256;
        int row = i >> 4, q = i & 15;
        CP_ASYNC16(smb + (uint32_t)(row * WROW + q * 16),
                   Wg + (uint64_t)(row * 256 + q * 16), 16u);
    }
    CP_COMMIT();

    // A loader helper offsets: 1024 x 16B chunks per tile, 4 per thread
    // chunk i: row = i>>4, q = i&15
    auto issue_A = [&](int tile, int buf) {
        int m0 = tile * 64;
        uint32_t stA = smb + SM_A_OFF + (uint32_t)buf * SM_A_BYTES;
        #pragma unroll
        for (int j = 0; j < 4; j++) {
            int i = t + j * 256;
            int row = i >> 4, q = i & 15;
            int gr = m0 + row;
            uint32_t ok = (gr < n) ? 16u : 0u;
            CP_ASYNC16(stA + (uint32_t)(row * WROW + q * 16),
                       Xg + ((uint64_t)(uint32_t)gr * 256 + q * 16), ok);
        }
        CP_COMMIT();
    };

    int tile = blockIdx.x;
    if (tile < ntiles) issue_A(tile, 0);

    // ldmatrix lane maps
    int lr  = (lane & 7) + ((lane >> 3) & 1) * 8;
    int lk8 = (lane >> 4) * 8;
    int bg  = lane >> 3;
    int br_ = (lane & 7) + ((bg >> 1) & 1) * 8;
    int bk8 = (bg & 1) * 8;

    int buf = 0;
    for (; tile < ntiles; tile += gridDim.x, buf ^= 1) {
        int m0 = tile * 64;

        CP_WAIT0();            // W (first iter) + A(tile) complete
        __syncthreads();

        int ntile = tile + gridDim.x;
        if (ntile < ntiles) issue_A(ntile, buf ^ 1);

        float accT[2][4][4], accP[2][4][4];
        #pragma unroll
        for (int mt = 0; mt < 2; mt++)
            #pragma unroll
            for (int nt = 0; nt < 4; nt++)
                #pragma unroll
                for (int r = 0; r < 4; r++) { accT[mt][nt][r] = 0.f; accP[mt][nt][r] = 0.f; }

        uint32_t stA = smb + SM_A_OFF + (uint32_t)buf * SM_A_BYTES;

        #pragma unroll
        for (int ks = 0; ks < 8; ks++) {
            int k = ks * 16;
            uint32_t aF[2][4];
            #pragma unroll
            for (int mt = 0; mt < 2; mt++) {
                uint32_t ad = stA + (uint32_t)((warp_m * 32 + mt * 16 + lr) * WROW + (k + lk8) * 2);
                LDMX4(aF[mt][0], aF[mt][1], aF[mt][2], aF[mt][3], ad);
            }
            {
                uint32_t bt[4][2];
                #pragma unroll
                for (int nh = 0; nh < 2; nh++) {
                    uint32_t bd = smb + (uint32_t)((warp_n * 32 + nh * 16 + br_) * WROW + (k + bk8) * 2);
                    LDMX4(bt[nh * 2][0], bt[nh * 2][1], bt[nh * 2 + 1][0], bt[nh * 2 + 1][1], bd);
                }
                #pragma unroll
                for (int mt = 0; mt < 2; mt++)
                    #pragma unroll
                    for (int nt = 0; nt < 4; nt++)
                        MMA16816F(accT[mt][nt], aF[mt][0], aF[mt][1], aF[mt][2], aF[mt][3],
                                  bt[nt][0], bt[nt][1]);
            }
            {
                uint32_t bp[4][2];
                #pragma unroll
                for (int nh = 0; nh < 2; nh++) {
                    uint32_t bd = smb + (uint32_t)((128 + warp_n * 32 + nh * 16 + br_) * WROW + (k + bk8) * 2);
                    LDMX4(bp[nh * 2][0], bp[nh * 2][1], bp[nh * 2 + 1][0], bp[nh * 2 + 1][1], bd);
                }
                #pragma unroll
                for (int mt = 0; mt < 2; mt++)
                    #pragma unroll
                    for (int nt = 0; nt < 4; nt++)
                        MMA16816F(accP[mt][nt], aF[mt][0], aF[mt][1], aF[mt][2], aF[mt][3],
                                  bp[nt][0], bp[nt][1]);
            }
        }

        // epilogue: g_Ch = fp16(theta); g_Dh = fp16(phi - theta + (tb+pb))
        #pragma unroll
        for (int mt = 0; mt < 2; mt++) {
            #pragma unroll
            for (int nt = 0; nt < 4; nt++) {
                int f = warp_n * 32 + nt * 8 + (lane & 3) * 2;
                float bias0 = __ldg(&tb[f]) + __ldg(&pb[f]);
                float bias1 = __ldg(&tb[f + 1]) + __ldg(&pb[f + 1]);
                int m = m0 + warp_m * 32 + mt * 16 + (lane >> 2);
                float* c = accT[mt][nt];
                float* p = accP[mt][nt];
                if (m < n) {
                    *(__half2*)(g_Ch + (size_t)m * FEAT + f) = __floats2half2_rn(c[0], c[1]);
                    *(__half2*)(g_Dh + (size_t)m * FEAT + f) =
                        __floats2half2_rn(p[0] - c[0] + bias0, p[1] - c[1] + bias1);
                }
                if (m + 8 < n) {
                    *(__half2*)(g_Ch + (size_t)(m + 8) * FEAT + f) = __floats2half2_rn(c[2], c[3]);
                    *(__half2*)(g_Dh + (size_t)(m + 8) * FEAT + f) =
                        __floats2half2_rn(p[2] - c[2] + bias0, p[3] - c[3] + bias1);
                }
            }
        }
        __syncthreads();   // all warps done with A buf before it is refilled
    }
}

// ---------------- gather-max: 1 warp/node, uint2, MLP=2 (R11 exact) --------
__device__ __forceinline__ uint32_t hmax2u(uint32_t x, uint32_t y) {
    __half2 r = __hmax2(*(__half2*)&x, *(__half2*)&y);
    return *(uint32_t*)&r;
}

__global__ void gather_kernel(float* __restrict__ dout, int layer, int n) {
    int gw = (blockIdx.x * blockDim.x + threadIdx.x) >> 5;
    int lane = threadIdx.x & 31;
    if (gw >= n) return;

    int deg = g_cur[gw];
    const int* lst = g_csr + gw * CAP;
    const uint2* C2 = (const uint2*)g_Ch;

    // hoisted D load (independent of edge loop)
    uint2 dv = __ldg(&((const uint2*)g_Dh)[(size_t)gw * 32 + lane]);

    const uint32_t NEG = 0xFBFFFBFFu;  // -65504 x2
    uint32_t a0 = NEG, a1 = NEG, b0 = NEG, b1 = NEG;

    int e = 0;
    for (; e + 1 < deg; e += 2) {
        int s0 = __ldg(&lst[e]);          // premultiplied src*32
        int s1 = __ldg(&lst[e + 1]);
        uint2 v0 = __ldg(&C2[(size_t)(uint32_t)(s0 + lane)]);
        uint2 v1 = __ldg(&C2[(size_t)(uint32_t)(s1 + lane)]);
        a0 = hmax2u(a0, v0.x); a1 = hmax2u(a1, v0.y);
        b0 = hmax2u(b0, v1.x); b1 = hmax2u(b1, v1.y);
    }
    if (e < deg) {
        int s0 = __ldg(&lst[e]);
        uint2 v0 = __ldg(&C2[(size_t)(uint32_t)(s0 + lane)]);
        a0 = hmax2u(a0, v0.x); a1 = hmax2u(a1, v0.y);
    }
    a0 = hmax2u(a0, b0);
    a1 = hmax2u(a1, b1);

    float2 m01 = __half22float2(*(__half2*)&a0);
    float2 m23 = __half22float2(*(__half2*)&a1);
    float2 d01 = __half22float2(*(__half2*)&dv.x);
    float2 d23 = __half22float2(*(__half2*)&dv.y);

    float4 o;
    o.x = fmaxf(0.f, d01.x + m01.x);
    o.y = fmaxf(0.f, d01.y + m01.y);
    o.z = fmaxf(0.f, d23.x + m23.x);
    o.w = fmaxf(0.f, d23.y + m23.y);

    if (layer == 3) {
        ((float4*)dout)[(size_t)gw * 32 + lane] = o;
        if (lane == 0) g_cur[gw] = 0;     // re-arm bucket counters for next run
    } else {
        __half2 p0 = __floats2half2_rn(o.x, o.y);
        __half2 p1 = __floats2half2_rn(o.z, o.w);
        uint2 xv;
        xv.x = *(uint32_t*)&p0;
        xv.y = *(uint32_t*)&p1;
        *(uint2*)(g_Xf + (size_t)gw * FEAT + lane * 4) = xv;
    }
}

// ---------------- launch ----------------------------------------------------
extern "C" void kernel_launch(void* const* d_in, const int* in_sizes, int n_in,
                              void* d_out, int out_size) {
    const float* feats = (const float*)d_in[0];
    const int*   src   = (const int*)d_in[1];
    const int*   dst   = (const int*)d_in[2];
    const float* tw    = (const float*)d_in[3];
    const float* tb    = (const float*)d_in[4];
    const float* pw    = (const float*)d_in[5];
    const float* pb    = (const float*)d_in[6];

    int n = in_sizes[0] / FEAT;
    int e = in_sizes[1];
    if (n > MAXN) n = MAXN;
    if (e > MAXE) e = MAXE;

    static int smem_set = 0;
    if (!smem_set) {
        cudaFuncSetAttribute(gemm_mma_kernel,
                             cudaFuncAttributeMaxDynamicSharedMemorySize, GEMM_SMEM);
        smem_set = 1;
    }

    // fused setup: X/W fp16 convert + bucket scatter (g_cur pre-zeroed)
    setup_kernel<<<(n * FEAT + 255) / 256, 256>>>(feats, tw, pw, src, dst, n, e);

    int ntiles = (n + 63) / 64;
    int pgrid = ntiles < 296 ? ntiles : 296;   // 148 SMs x 2 CTAs
    int warp_blocks = (n * 32 + 255) / 256;

    for (int l = 0; l < 4; l++) {
        gemm_mma_kernel<<<pgrid, 256, GEMM_SMEM>>>(l, tb + l * FEAT, pb + l * FEAT, n, ntiles);
        gather_kernel<<<warp_blocks, 256>>>((float*)d_out, l, n);
    }
}